// round 16
// baseline (speedup 1.0000x reference)
#include <cuda_runtime.h>
#include <cuda_fp16.h>
#include <cstdint>

// Problem constants
#define N_ROWS 32768
#define DDIM   512
#define KCODES 4096

// Coarse tiling (fp16 HMMA, f16 accumulate)
#define MT 128                 // rows per CTA
#define NT 128                 // codes per chunk
#define BK 64                  // K fp16 per SMEM tile (128B rows)
#define NCHUNKS (KCODES / NT)          // 32
#define STAGE_BYTES 32768      // A 16KB + B 16KB
#define SMEM_TOTAL (2 * STAGE_BYTES)   // 65536

#define NCAND 4

// ---------------- scratch ----------------
__device__ __half g_Ah[(size_t)N_ROWS * DDIM];
__device__ __half g_Ch[(size_t)KCODES * DDIM];
__device__ float g_cnorm[KCODES];

// ---------------- PTX helpers ----------------
__device__ __forceinline__ uint32_t smem_to_u32(const void* p) {
    uint32_t a;
    asm("{ .reg .u64 t; cvta.to.shared.u64 t, %1; cvt.u32.u64 %0, t; }" : "=r"(a) : "l"(p));
    return a;
}
__device__ __forceinline__ void cp_async16(uint32_t dst, const void* src) {
    asm volatile("cp.async.cg.shared.global [%0], [%1], 16;" :: "r"(dst), "l"(src) : "memory");
}
#define CP_COMMIT() asm volatile("cp.async.commit_group;" ::: "memory")
#define CP_WAIT(n)  asm volatile("cp.async.wait_group %0;" :: "n"(n) : "memory")

__device__ __forceinline__ void ldsm_x4(uint32_t& r0, uint32_t& r1, uint32_t& r2,
                                        uint32_t& r3, uint32_t addr) {
    asm volatile("ldmatrix.sync.aligned.m8n8.x4.shared.b16 {%0,%1,%2,%3}, [%4];"
                 : "=r"(r0), "=r"(r1), "=r"(r2), "=r"(r3) : "r"(addr));
}
// fp16 x fp16 -> fp16 accumulate
__device__ __forceinline__ void mma16816_f16(uint32_t* d, const uint32_t* a,
                                             uint32_t b0, uint32_t b1) {
    asm volatile(
        "mma.sync.aligned.m16n8k16.row.col.f16.f16.f16.f16 "
        "{%0,%1}, {%2,%3,%4,%5}, {%6,%7}, {%0,%1};"
        : "+r"(d[0]), "+r"(d[1])
        : "r"(a[0]), "r"(a[1]), "r"(a[2]), "r"(a[3]), "r"(b0), "r"(b1));
}

// ---------------------------------------------------------------------------
// Prep: codebook only — fp16 convert + exact fp32 ||c||^2. 4096 blocks.
// ---------------------------------------------------------------------------
__global__ void prep_codebook_kernel(const float* __restrict__ cb) {
    const int k = blockIdx.x;
    float4 v = reinterpret_cast<const float4*>(cb + (size_t)k * DDIM)[threadIdx.x];
    __half h[4] = {__float2half_rn(v.x), __float2half_rn(v.y),
                   __float2half_rn(v.z), __float2half_rn(v.w)};
    reinterpret_cast<uint2*>(g_Ch)[k * (DDIM / 4) + threadIdx.x] =
        *reinterpret_cast<uint2*>(h);
    float s = v.x * v.x + v.y * v.y + v.z * v.z + v.w * v.w;
#pragma unroll
    for (int o = 16; o > 0; o >>= 1) s += __shfl_xor_sync(0xffffffffu, s, o);
    __shared__ float ws[4];
    if ((threadIdx.x & 31) == 0) ws[threadIdx.x >> 5] = s;
    __syncthreads();
    if (threadIdx.x == 0) g_cnorm[k] = ws[0] + ws[1] + ws[2] + ws[3];
}

// ---------------------------------------------------------------------------
// Fused: lazy per-slice A conversion + coarse GEMM + exact refine.
// Grid 256 CTAs x 256 threads, 2 CTAs/SM. 8 warps (4m x 2n), warp tile 32x64.
// ---------------------------------------------------------------------------
__global__ void __launch_bounds__(256, 2)
vq_fused_kernel(const float* __restrict__ cb, const float* __restrict__ x,
                float* __restrict__ out) {
    extern __shared__ char smem[];
    const uint32_t sb = smem_to_u32(smem);
    const int tid  = threadIdx.x;
    const int lane = tid & 31;
    const int warp = tid >> 5;
    const int wm = warp >> 1;          // 0..3 (32 rows each)
    const int wn = warp & 1;           // 0..1 (64 codes each)
    const int r0 = blockIdx.x * MT;

    const int sub  = lane >> 3;
    const int lrow = (sub & 1) * 8 + (lane & 7);
    const int lchk = sub >> 1;

    // ---- loader constants ----
    const int ldr = tid >> 3;          // 0..31
    const int ldc = tid & 7;
    const uint32_t swl = (uint32_t)(ldr * 128 + ((ldc ^ (ldr & 7)) << 4));
    const uint32_t dA[2] = { sb + swl, sb + STAGE_BYTES + swl };
    const uint32_t dB[2] = { sb + 16384 + swl, sb + STAGE_BYTES + 16384 + swl };
    const char* pA = (const char*)g_Ah + ((size_t)(r0 + ldr) * DDIM + ldc * 8) * 2;
    const char* pB = (const char*)g_Ch + ((size_t)ldr * DDIM + ldc * 8) * 2;

    // ---- per-slice conversion sources/dests (slice s = columns [s*64, s*64+64)) ----
    const float4* xs4 = reinterpret_cast<const float4*>(x + (size_t)r0 * DDIM);
    uint2* ad2 = reinterpret_cast<uint2*>(g_Ah + (size_t)r0 * DDIM);

    // ---- LDSM base addresses (addr = base ^ (kk<<5)) ----
    uint32_t fullA[2][2], fullB[2][4];
#pragma unroll
    for (int mi = 0; mi < 2; ++mi) {
        int r = wm * 32 + mi * 16 + lrow;
        uint32_t b = (uint32_t)(r * 128 + (((r & 7) ^ lchk) << 4));
        fullA[0][mi] = sb + b;
        fullA[1][mi] = sb + STAGE_BYTES + b;
    }
#pragma unroll
    for (int ni = 0; ni < 4; ++ni) {
        int r = wn * 64 + ni * 16 + lrow;
        uint32_t b = (uint32_t)(r * 128 + (((r & 7) ^ lchk) << 4));
        fullB[0][ni] = sb + 16384 + b;
        fullB[1][ni] = sb + STAGE_BYTES + 16384 + b;
    }

    // ---- prologue part 1: B tile 0 load (independent of A conversion) ----
#pragma unroll
    for (int i = 0; i < 4; ++i)
        cp_async16(dB[0] + i * 4096, pB + i * 32768);
    CP_COMMIT();

    // ---- convert slices 0 and 1 only (rest lazily during chunk 0) ----
#pragma unroll
    for (int s = 0; s < 2; ++s) {
#pragma unroll
        for (int i = 0; i < 8; ++i) {
            int idx = tid + i * 256;                         // 0..2047
            int gidx = ((idx >> 4) << 7) + (s << 4) + (idx & 15);
            float4 v = xs4[gidx];
            __half h[4] = {__float2half_rn(v.x), __float2half_rn(v.y),
                           __float2half_rn(v.z), __float2half_rn(v.w)};
            ad2[gidx] = *reinterpret_cast<uint2*>(h);
        }
    }
    __threadfence_block();
    __syncthreads();

    // ---- prologue part 2: A tile 0 (slice 0) ----
#pragma unroll
    for (int i = 0; i < 4; ++i)
        cp_async16(dA[0] + i * 4096, pA + i * 32768);
    CP_COMMIT();

    uint32_t acc[2][8][2];
#pragma unroll
    for (int mi = 0; mi < 2; ++mi)
#pragma unroll
        for (int n8 = 0; n8 < 8; ++n8) { acc[mi][n8][0] = 0u; acc[mi][n8][1] = 0u; }

    // per row-slot TOP-2 (slot = mi*2 + rowhalf)
    float v0[4], v1[4];
    int   i0[4], i1[4];
#pragma unroll
    for (int s = 0; s < 4; ++s) { v0[s] = v1[s] = 3.0e38f; i0[s] = i1[s] = 0x7fffffff; }

#pragma unroll 1
    for (int chunk = 0; chunk < NCHUNKS; ++chunk) {
#pragma unroll
        for (int kt = 0; kt < 8; ++kt) {
            CP_WAIT(0);
            __syncthreads();

            // issue next tile into the other stage
            if (kt < 7) {
#pragma unroll
                for (int i = 0; i < 4; ++i) {
                    cp_async16(dA[(kt + 1) & 1] + i * 4096,
                               pA + (kt + 1) * 128 + i * 32768);
                    cp_async16(dB[(kt + 1) & 1] + i * 4096,
                               pB + (kt + 1) * 128 + i * 32768);
                }
                CP_COMMIT();
            } else if (chunk < NCHUNKS - 1) {
                const char* pBn = pB + 131072;
#pragma unroll
                for (int i = 0; i < 4; ++i) {
                    cp_async16(dA[0] + i * 4096, pA + i * 32768);
                    cp_async16(dB[0] + i * 4096, pBn + i * 32768);
                }
                CP_COMMIT();
            }

            // compute on stage kt&1
            {
                const int s = kt & 1;
#pragma unroll
                for (int kk = 0; kk < 4; ++kk) {
                    uint32_t a[2][4];
#pragma unroll
                    for (int mi = 0; mi < 2; ++mi)
                        ldsm_x4(a[mi][0], a[mi][1], a[mi][2], a[mi][3],
                                fullA[s][mi] ^ (uint32_t)(kk << 5));
                    uint32_t bf[4][4];
#pragma unroll
                    for (int ni = 0; ni < 4; ++ni)
                        ldsm_x4(bf[ni][0], bf[ni][1], bf[ni][2], bf[ni][3],
                                fullB[s][ni] ^ (uint32_t)(kk << 5));
#pragma unroll
                    for (int mi = 0; mi < 2; ++mi)
#pragma unroll
                        for (int n8 = 0; n8 < 8; ++n8)
                            mma16816_f16(acc[mi][n8], a[mi],
                                         bf[n8 >> 1][n8 & 1], bf[n8 >> 1][(n8 & 1) + 2]);
                }
            }

            // lazy conversion of A slice kt+2 during chunk 0 (kt = 0..5).
            // Completes before the next tile's __syncthreads; its consumer
            // cp.async (slice kt+2) is issued at tile kt+1, after that sync.
            if (chunk == 0 && kt < 6) {
                const int s = kt + 2;
#pragma unroll
                for (int i = 0; i < 8; ++i) {
                    int idx = tid + i * 256;
                    int gidx = ((idx >> 4) << 7) + (s << 4) + (idx & 15);
                    float4 v = xs4[gidx];
                    __half h[4] = {__float2half_rn(v.x), __float2half_rn(v.y),
                                   __float2half_rn(v.z), __float2half_rn(v.w)};
                    ad2[gidx] = *reinterpret_cast<uint2*>(h);
                }
                __threadfence_block();
            }

            // chunk epilogue: TOP-2 per slot
            if (kt == 7) {
                const int c0 = chunk * NT;
#pragma unroll
                for (int n8 = 0; n8 < 8; ++n8) {
                    const int col = c0 + wn * 64 + n8 * 8 + 2 * (lane & 3);
                    const float cn0 = __ldg(&g_cnorm[col]);
                    const float cn1 = __ldg(&g_cnorm[col + 1]);
#pragma unroll
                    for (int mi = 0; mi < 2; ++mi) {
#pragma unroll
                        for (int r = 0; r < 2; ++r) {
                            const int slot = mi * 2 + r;
                            float2 f = __half22float2(
                                *reinterpret_cast<__half2*>(&acc[mi][n8][r]));
                            float d0 = fmaf(-2.f, f.x, cn0);
                            float d1 = fmaf(-2.f, f.y, cn1);
                            if (d0 < v1[slot]) {
                                if (d0 < v0[slot]) {
                                    v1[slot] = v0[slot]; i1[slot] = i0[slot];
                                    v0[slot] = d0;       i0[slot] = col;
                                } else { v1[slot] = d0; i1[slot] = col; }
                            }
                            if (d1 < v1[slot]) {
                                if (d1 < v0[slot]) {
                                    v1[slot] = v0[slot]; i1[slot] = i0[slot];
                                    v0[slot] = d1;       i0[slot] = col + 1;
                                } else { v1[slot] = d1; i1[slot] = col + 1; }
                            }
                            acc[mi][n8][r] = 0u;
                        }
                    }
                }
            }
        }
        pB += 131072;   // next 128 codebook rows
    }

    // ---- Merge 8 threads x 2 entries per row -> top-4 per row (in smem) ----
    __syncthreads();
    float* mv   = reinterpret_cast<float*>(smem);            // [128][16]
    int*   md   = reinterpret_cast<int*>(smem + 8192);       // [128][16]
    int*   cand = reinterpret_cast<int*>(smem + 16384);      // [128][4]
#pragma unroll
    for (int slot = 0; slot < 4; ++slot) {
        const int mi = slot >> 1, rh = slot & 1;
        const int row = wm * 32 + mi * 16 + rh * 8 + (lane >> 2);
        const int col = wn * 8 + (lane & 3) * 2;
        mv[row * 16 + col]     = v0[slot];
        md[row * 16 + col]     = i0[slot];
        mv[row * 16 + col + 1] = v1[slot];
        md[row * 16 + col + 1] = i1[slot];
    }
    __syncthreads();
    if (tid < MT) {
        float tv[4] = {3.0e38f, 3.0e38f, 3.0e38f, 3.0e38f};
        int   ti[4] = {0x7fffffff, 0x7fffffff, 0x7fffffff, 0x7fffffff};
#pragma unroll 4
        for (int e = 0; e < 16; ++e) {
            float v = mv[tid * 16 + e];
            int   d = md[tid * 16 + e];
            if (v < tv[3] || (v == tv[3] && d < ti[3])) {
                tv[3] = v; ti[3] = d;
#pragma unroll
                for (int j = 3; j >= 1; --j) {
                    if (tv[j] < tv[j-1] || (tv[j] == tv[j-1] && ti[j] < ti[j-1])) {
                        float fv = tv[j]; tv[j] = tv[j-1]; tv[j-1] = fv;
                        int   fi = ti[j]; ti[j] = ti[j-1]; ti[j-1] = fi;
                    }
                }
            }
        }
#pragma unroll
        for (int j = 0; j < 4; ++j) cand[tid * 4 + j] = ti[j];
    }
    __syncthreads();

    // ---- Fused exact refine + gather: warp w refines rows [w*16, w*16+16) ----
#pragma unroll 1
    for (int rr = 0; rr < 16; ++rr) {
        const int row = warp * 16 + rr;
        const int n = r0 + row;

        float xr[16];
#pragma unroll
        for (int j = 0; j < 16; ++j) xr[j] = x[(size_t)n * DDIM + j * 32 + lane];

        float bv = 3.0e38f;
        int   bi = 0x7fffffff;
#pragma unroll
        for (int c = 0; c < NCAND; ++c) {
            const int k = cand[row * 4 + c];
            const float* crow = cb + (size_t)k * DDIM;
            float s = 0.f;
#pragma unroll
            for (int j = 0; j < 16; ++j) s = fmaf(xr[j], __ldg(crow + j * 32 + lane), s);
#pragma unroll
            for (int o = 16; o > 0; o >>= 1) s += __shfl_xor_sync(0xffffffffu, s, o);
            float d2 = fmaf(-2.f, s, __ldg(&g_cnorm[k]));
            if (d2 < bv || (d2 == bv && k < bi)) { bv = d2; bi = k; }
        }

        const float* q = cb + (size_t)bi * DDIM;
#pragma unroll
        for (int j = 0; j < 16; ++j) {
            float qv = __ldg(q + j * 32 + lane);
            float xv = xr[j];
            out[(size_t)n * DDIM + j * 32 + lane] = (qv - xv) + xv;
        }
    }
}

// ---------------------------------------------------------------------------
extern "C" void kernel_launch(void* const* d_in, const int* in_sizes, int n_in,
                              void* d_out, int out_size) {
    const float* inputs   = (const float*)d_in[0];
    const float* codebook = (const float*)d_in[1];
    float* out = (float*)d_out;

    cudaFuncSetAttribute(vq_fused_kernel, cudaFuncAttributeMaxDynamicSharedMemorySize,
                         SMEM_TOTAL);

    prep_codebook_kernel<<<KCODES, 128>>>(codebook);
    vq_fused_kernel<<<N_ROWS / MT, 256, SMEM_TOTAL>>>(codebook, inputs, out);
}

// round 17
// speedup vs baseline: 1.0780x; 1.0780x over previous
#include <cuda_runtime.h>
#include <cuda_fp16.h>
#include <cstdint>

// Problem constants
#define N_ROWS 32768
#define DDIM   512
#define KCODES 4096

// Coarse tiling (fp16 HMMA, f16 accumulate)
#define MT 128                 // rows per CTA
#define NT 128                 // codes per chunk
#define BK 64                  // K fp16 per SMEM tile (128B rows)
#define NCHUNKS (KCODES / NT)          // 32
#define STAGE_BYTES 32768      // A 16KB + B 16KB
#define SMEM_TOTAL (2 * STAGE_BYTES)   // 65536

#define NCAND 4
#define GAP_THRESH 1.5f        // coarse-gap gate (~15 sigma of fp16 noise)

// ---------------- scratch ----------------
__device__ __half g_Ah[(size_t)N_ROWS * DDIM];
__device__ __half g_Ch[(size_t)KCODES * DDIM];
__device__ float g_cnorm[KCODES];

// ---------------- PTX helpers ----------------
__device__ __forceinline__ uint32_t smem_to_u32(const void* p) {
    uint32_t a;
    asm("{ .reg .u64 t; cvta.to.shared.u64 t, %1; cvt.u32.u64 %0, t; }" : "=r"(a) : "l"(p));
    return a;
}
__device__ __forceinline__ void cp_async16(uint32_t dst, const void* src) {
    asm volatile("cp.async.cg.shared.global [%0], [%1], 16;" :: "r"(dst), "l"(src) : "memory");
}
#define CP_COMMIT() asm volatile("cp.async.commit_group;" ::: "memory")
#define CP_WAIT(n)  asm volatile("cp.async.wait_group %0;" :: "n"(n) : "memory")

__device__ __forceinline__ void ldsm_x4(uint32_t& r0, uint32_t& r1, uint32_t& r2,
                                        uint32_t& r3, uint32_t addr) {
    asm volatile("ldmatrix.sync.aligned.m8n8.x4.shared.b16 {%0,%1,%2,%3}, [%4];"
                 : "=r"(r0), "=r"(r1), "=r"(r2), "=r"(r3) : "r"(addr));
}
// fp16 x fp16 -> fp16 accumulate
__device__ __forceinline__ void mma16816_f16(uint32_t* d, const uint32_t* a,
                                             uint32_t b0, uint32_t b1) {
    asm volatile(
        "mma.sync.aligned.m16n8k16.row.col.f16.f16.f16.f16 "
        "{%0,%1}, {%2,%3,%4,%5}, {%6,%7}, {%0,%1};"
        : "+r"(d[0]), "+r"(d[1])
        : "r"(a[0]), "r"(a[1]), "r"(a[2]), "r"(a[3]), "r"(b0), "r"(b1));
}

// ---------------------------------------------------------------------------
// Prep: codebook only — fp16 convert + exact fp32 ||c||^2. 4096 blocks.
// ---------------------------------------------------------------------------
__global__ void prep_codebook_kernel(const float* __restrict__ cb) {
    const int k = blockIdx.x;
    float4 v = reinterpret_cast<const float4*>(cb + (size_t)k * DDIM)[threadIdx.x];
    __half h[4] = {__float2half_rn(v.x), __float2half_rn(v.y),
                   __float2half_rn(v.z), __float2half_rn(v.w)};
    reinterpret_cast<uint2*>(g_Ch)[k * (DDIM / 4) + threadIdx.x] =
        *reinterpret_cast<uint2*>(h);
    float s = v.x * v.x + v.y * v.y + v.z * v.z + v.w * v.w;
#pragma unroll
    for (int o = 16; o > 0; o >>= 1) s += __shfl_xor_sync(0xffffffffu, s, o);
    __shared__ float ws[4];
    if ((threadIdx.x & 31) == 0) ws[threadIdx.x >> 5] = s;
    __syncthreads();
    if (threadIdx.x == 0) g_cnorm[k] = ws[0] + ws[1] + ws[2] + ws[3];
}

// ---------------------------------------------------------------------------
// Fused: per-CTA A conversion + coarse GEMM + gap-gated exact refine.
// Grid 256 CTAs x 256 threads, 2 CTAs/SM. 8 warps (4m x 2n), warp tile 32x64.
// ---------------------------------------------------------------------------
__global__ void __launch_bounds__(256, 2)
vq_fused_kernel(const float* __restrict__ cb, const float* __restrict__ x,
                float* __restrict__ out) {
    extern __shared__ char smem[];
    const uint32_t sb = smem_to_u32(smem);
    const int tid  = threadIdx.x;
    const int lane = tid & 31;
    const int warp = tid >> 5;
    const int wm = warp >> 1;          // 0..3 (32 rows each)
    const int wn = warp & 1;           // 0..1 (64 codes each)
    const int r0 = blockIdx.x * MT;

    const int sub  = lane >> 3;
    const int lrow = (sub & 1) * 8 + (lane & 7);
    const int lchk = sub >> 1;

    // ---- loader constants ----
    const int ldr = tid >> 3;          // 0..31
    const int ldc = tid & 7;
    const uint32_t swl = (uint32_t)(ldr * 128 + ((ldc ^ (ldr & 7)) << 4));
    const uint32_t dA[2] = { sb + swl, sb + STAGE_BYTES + swl };
    const uint32_t dB[2] = { sb + 16384 + swl, sb + STAGE_BYTES + 16384 + swl };
    const char* pA = (const char*)g_Ah + ((size_t)(r0 + ldr) * DDIM + ldc * 8) * 2;
    const char* pB = (const char*)g_Ch + ((size_t)ldr * DDIM + ldc * 8) * 2;

    // ---- LDSM base addresses (addr = base ^ (kk<<5)) ----
    uint32_t fullA[2][2], fullB[2][4];
#pragma unroll
    for (int mi = 0; mi < 2; ++mi) {
        int r = wm * 32 + mi * 16 + lrow;
        uint32_t b = (uint32_t)(r * 128 + (((r & 7) ^ lchk) << 4));
        fullA[0][mi] = sb + b;
        fullA[1][mi] = sb + STAGE_BYTES + b;
    }
#pragma unroll
    for (int ni = 0; ni < 4; ++ni) {
        int r = wn * 64 + ni * 16 + lrow;
        uint32_t b = (uint32_t)(r * 128 + (((r & 7) ^ lchk) << 4));
        fullB[0][ni] = sb + 16384 + b;
        fullB[1][ni] = sb + STAGE_BYTES + 16384 + b;
    }

    // ---- prologue part 1: B tile 0 load (independent of A conversion) ----
#pragma unroll
    for (int i = 0; i < 4; ++i)
        cp_async16(dB[0] + i * 4096, pB + i * 32768);
    CP_COMMIT();

    // ---- convert this CTA's 128 input rows fp32 -> fp16 into g_Ah slice ----
    {
        const float4* xs = reinterpret_cast<const float4*>(x + (size_t)r0 * DDIM);
        uint2* ad = reinterpret_cast<uint2*>(g_Ah + (size_t)r0 * DDIM);
#pragma unroll 4
        for (int i = 0; i < 64; ++i) {
            int idx = tid + i * 256;
            float4 v = xs[idx];
            __half h[4] = {__float2half_rn(v.x), __float2half_rn(v.y),
                           __float2half_rn(v.z), __float2half_rn(v.w)};
            ad[idx] = *reinterpret_cast<uint2*>(h);
        }
    }
    __threadfence_block();
    __syncthreads();

    // ---- prologue part 2: A tile 0 ----
#pragma unroll
    for (int i = 0; i < 4; ++i)
        cp_async16(dA[0] + i * 4096, pA + i * 32768);
    CP_COMMIT();

    uint32_t acc[2][8][2];
#pragma unroll
    for (int mi = 0; mi < 2; ++mi)
#pragma unroll
        for (int n8 = 0; n8 < 8; ++n8) { acc[mi][n8][0] = 0u; acc[mi][n8][1] = 0u; }

    // per row-slot TOP-2 (slot = mi*2 + rowhalf)
    float v0[4], v1[4];
    int   i0[4], i1[4];
#pragma unroll
    for (int s = 0; s < 4; ++s) { v0[s] = v1[s] = 3.0e38f; i0[s] = i1[s] = 0x7fffffff; }

#pragma unroll 1
    for (int chunk = 0; chunk < NCHUNKS; ++chunk) {
#pragma unroll
        for (int kt = 0; kt < 8; ++kt) {
            CP_WAIT(0);
            __syncthreads();

            // issue next tile into the other stage
            if (kt < 7) {
#pragma unroll
                for (int i = 0; i < 4; ++i) {
                    cp_async16(dA[(kt + 1) & 1] + i * 4096,
                               pA + (kt + 1) * 128 + i * 32768);
                    cp_async16(dB[(kt + 1) & 1] + i * 4096,
                               pB + (kt + 1) * 128 + i * 32768);
                }
                CP_COMMIT();
            } else if (chunk < NCHUNKS - 1) {
                const char* pBn = pB + 131072;
#pragma unroll
                for (int i = 0; i < 4; ++i) {
                    cp_async16(dA[0] + i * 4096, pA + i * 32768);
                    cp_async16(dB[0] + i * 4096, pBn + i * 32768);
                }
                CP_COMMIT();
            }

            // compute on stage kt&1
            {
                const int s = kt & 1;
#pragma unroll
                for (int kk = 0; kk < 4; ++kk) {
                    uint32_t a[2][4];
#pragma unroll
                    for (int mi = 0; mi < 2; ++mi)
                        ldsm_x4(a[mi][0], a[mi][1], a[mi][2], a[mi][3],
                                fullA[s][mi] ^ (uint32_t)(kk << 5));
                    uint32_t bf[4][4];
#pragma unroll
                    for (int ni = 0; ni < 4; ++ni)
                        ldsm_x4(bf[ni][0], bf[ni][1], bf[ni][2], bf[ni][3],
                                fullB[s][ni] ^ (uint32_t)(kk << 5));
#pragma unroll
                    for (int mi = 0; mi < 2; ++mi)
#pragma unroll
                        for (int n8 = 0; n8 < 8; ++n8)
                            mma16816_f16(acc[mi][n8], a[mi],
                                         bf[n8 >> 1][n8 & 1], bf[n8 >> 1][(n8 & 1) + 2]);
                }
            }

            // chunk epilogue: TOP-2 per slot
            if (kt == 7) {
                const int c0 = chunk * NT;
#pragma unroll
                for (int n8 = 0; n8 < 8; ++n8) {
                    const int col = c0 + wn * 64 + n8 * 8 + 2 * (lane & 3);
                    const float cn0 = __ldg(&g_cnorm[col]);
                    const float cn1 = __ldg(&g_cnorm[col + 1]);
#pragma unroll
                    for (int mi = 0; mi < 2; ++mi) {
#pragma unroll
                        for (int r = 0; r < 2; ++r) {
                            const int slot = mi * 2 + r;
                            float2 f = __half22float2(
                                *reinterpret_cast<__half2*>(&acc[mi][n8][r]));
                            float d0 = fmaf(-2.f, f.x, cn0);
                            float d1 = fmaf(-2.f, f.y, cn1);
                            if (d0 < v1[slot]) {
                                if (d0 < v0[slot]) {
                                    v1[slot] = v0[slot]; i1[slot] = i0[slot];
                                    v0[slot] = d0;       i0[slot] = col;
                                } else { v1[slot] = d0; i1[slot] = col; }
                            }
                            if (d1 < v1[slot]) {
                                if (d1 < v0[slot]) {
                                    v1[slot] = v0[slot]; i1[slot] = i0[slot];
                                    v0[slot] = d1;       i0[slot] = col + 1;
                                } else { v1[slot] = d1; i1[slot] = col + 1; }
                            }
                            acc[mi][n8][r] = 0u;
                        }
                    }
                }
            }
        }
        pB += 131072;   // next 128 codebook rows
    }

    // ---- Merge 8 threads x 2 entries per row -> top-4 + gap gate ----
    __syncthreads();
    float* mv    = reinterpret_cast<float*>(smem);            // [128][16]
    int*   md    = reinterpret_cast<int*>(smem + 8192);       // [128][16]
    int*   cand  = reinterpret_cast<int*>(smem + 16384);      // [128][4]
    int*   cflag = reinterpret_cast<int*>(smem + 18432);      // [128]
#pragma unroll
    for (int slot = 0; slot < 4; ++slot) {
        const int mi = slot >> 1, rh = slot & 1;
        const int row = wm * 32 + mi * 16 + rh * 8 + (lane >> 2);
        const int col = wn * 8 + (lane & 3) * 2;
        mv[row * 16 + col]     = v0[slot];
        md[row * 16 + col]     = i0[slot];
        mv[row * 16 + col + 1] = v1[slot];
        md[row * 16 + col + 1] = i1[slot];
    }
    __syncthreads();
    if (tid < MT) {
        float tv[4] = {3.0e38f, 3.0e38f, 3.0e38f, 3.0e38f};
        int   ti[4] = {0x7fffffff, 0x7fffffff, 0x7fffffff, 0x7fffffff};
#pragma unroll 4
        for (int e = 0; e < 16; ++e) {
            float v = mv[tid * 16 + e];
            int   d = md[tid * 16 + e];
            if (v < tv[3] || (v == tv[3] && d < ti[3])) {
                tv[3] = v; ti[3] = d;
#pragma unroll
                for (int j = 3; j >= 1; --j) {
                    if (tv[j] < tv[j-1] || (tv[j] == tv[j-1] && ti[j] < ti[j-1])) {
                        float fv = tv[j]; tv[j] = tv[j-1]; tv[j-1] = fv;
                        int   fi = ti[j]; ti[j] = ti[j-1]; ti[j-1] = fi;
                    }
                }
            }
        }
#pragma unroll
        for (int j = 0; j < 4; ++j) cand[tid * 4 + j] = ti[j];
        cflag[tid] = (tv[1] - tv[0] > GAP_THRESH) ? 1 : 0;
    }
    __syncthreads();

    // ---- Gap-gated refine + gather: warp w handles rows [w*16, w*16+16) ----
#pragma unroll 1
    for (int rr = 0; rr < 16; ++rr) {
        const int row = warp * 16 + rr;
        const int n = r0 + row;
        int bi = cand[row * 4];

        if (!cflag[row]) {
            // ambiguous: exact fp32 refine over 4 candidates
            float xr[16];
#pragma unroll
            for (int j = 0; j < 16; ++j) xr[j] = x[(size_t)n * DDIM + j * 32 + lane];
            float bv = 3.0e38f;
            bi = 0x7fffffff;
#pragma unroll
            for (int c = 0; c < NCAND; ++c) {
                const int k = cand[row * 4 + c];
                const float* crow = cb + (size_t)k * DDIM;
                float s = 0.f;
#pragma unroll
                for (int j = 0; j < 16; ++j) s = fmaf(xr[j], __ldg(crow + j * 32 + lane), s);
#pragma unroll
                for (int o = 16; o > 0; o >>= 1) s += __shfl_xor_sync(0xffffffffu, s, o);
                float d2 = fmaf(-2.f, s, __ldg(&g_cnorm[k]));
                if (d2 < bv || (d2 == bv && k < bi)) { bv = d2; bi = k; }
            }
        }

        // gather: out = q (reference STE leaves out == q up to fp32 dust)
        const float4* q4 = reinterpret_cast<const float4*>(cb + (size_t)bi * DDIM);
        float4* o4 = reinterpret_cast<float4*>(out + (size_t)n * DDIM);
#pragma unroll
        for (int j = 0; j < 4; ++j)
            o4[j * 32 + lane] = q4[j * 32 + lane];
    }
}

// ---------------------------------------------------------------------------
extern "C" void kernel_launch(void* const* d_in, const int* in_sizes, int n_in,
                              void* d_out, int out_size) {
    const float* inputs   = (const float*)d_in[0];
    const float* codebook = (const float*)d_in[1];
    float* out = (float*)d_out;

    cudaFuncSetAttribute(vq_fused_kernel, cudaFuncAttributeMaxDynamicSharedMemorySize,
                         SMEM_TOTAL);

    prep_codebook_kernel<<<KCODES, 128>>>(codebook);
    vq_fused_kernel<<<N_ROWS / MT, 256, SMEM_TOTAL>>>(codebook, inputs, out);
}